// round 13
// baseline (speedup 1.0000x reference)
#include <cuda_runtime.h>
#include <cuda_bf16.h>
#include <math_constants.h>
#include <cstdint>

// ============================================================================
// Problem constants
// ============================================================================
#define D        256
#define MROWS    32768
#define KCODES   8192
#define NTILE    64            // KCODES / 128
#define BM       128
#define BN       128
#define BK       16
#define TM       8
#define TN       8
#define NTHREADS 256

// dist kernel smem geometry:
//   zh resident: 128 rows x 256 k bf16, row stride 264 (528 B, 16B bank shift)
//   eh ring:     2 x (128 codes x 64 k bf16, row stride 72)
//   red:         128 x 2 float4 cross-warp reduce scratch
#define ZSB      264
#define ZTILEB   (128 * ZSB * 2)       // 67584
#define ESB      72
#define ETILEB   (128 * ESB * 2)       // 18432
#define EOFF     ZTILEB                // 67584
#define REDOFF   (ZTILEB + 2 * ETILEB) // 104448
#define DIST_SMEM (REDOFF + 4096)      // 108544 -> 2 CTAs/SM (217088 <= 228KB)

// proj kernel smem: 2 stages x 2 tiles x 16 x 132 floats
#define PROJ_SMEM (2 * 2 * BK * (BM + 4) * 4)   // 67584 B

// ============================================================================
// Device scratch (no cudaMalloc allowed)
// ============================================================================
__device__ float          g_cn[KCODES];
__device__ float          g_part[4096];
__device__ __nv_bfloat16  g_cbh[KCODES * D];
__device__ __nv_bfloat16  g_zh[MROWS * D];
__device__ float2         g_cv[(size_t)MROWS * NTILE];
__device__ int2           g_ci[(size_t)MROWS * NTILE];

// ============================================================================
// Helpers
// ============================================================================
__device__ __forceinline__ uint32_t smem_to_u32(const void* p) {
    uint32_t a;
    asm("{ .reg .u64 t; cvta.to.shared.u64 t, %1; cvt.u32.u64 %0, t; }"
        : "=r"(a) : "l"(p));
    return a;
}
__device__ __forceinline__ void cp16(uint32_t dst, const void* src) {
    asm volatile("cp.async.cg.shared.global [%0], [%1], 16;"
        :: "r"(dst), "l"(__cvta_generic_to_global(src)) : "memory");
}
__device__ __forceinline__ void ldsm_x4(uint32_t& r0, uint32_t& r1,
                                        uint32_t& r2, uint32_t& r3, uint32_t addr) {
    asm volatile("ldmatrix.sync.aligned.m8n8.x4.shared.b16 {%0,%1,%2,%3}, [%4];"
        : "=r"(r0), "=r"(r1), "=r"(r2), "=r"(r3) : "r"(addr));
}
__device__ __forceinline__ void mma16816(float* c, uint32_t a0, uint32_t a1,
                                         uint32_t a2, uint32_t a3,
                                         uint32_t b0, uint32_t b1) {
    asm volatile("mma.sync.aligned.m16n8k16.row.col.f32.bf16.bf16.f32 "
        "{%0,%1,%2,%3}, {%4,%5,%6,%7}, {%8,%9}, {%0,%1,%2,%3};"
        : "+f"(c[0]), "+f"(c[1]), "+f"(c[2]), "+f"(c[3])
        : "r"(a0), "r"(a1), "r"(a2), "r"(a3), "r"(b0), "r"(b1));
}
__device__ __forceinline__ void top2_merge(float& v0, int& i0, float& v1, int& i1,
                                           float w0, int j0, float w1, int j1) {
    if (w0 < v0) {
        if (v0 < w1) { v1 = v0; i1 = i0; } else { v1 = w1; i1 = j1; }
        v0 = w0; i0 = j0;
    } else if (w0 < v1) { v1 = w0; i1 = j0; }
}

// ============================================================================
// Kernel 1: fused codebook norms + bf16 hi-split (one pass over cb)
// ============================================================================
__global__ __launch_bounds__(256)
void cnsplit_kernel(const float* __restrict__ cb) {
    int row = blockIdx.x * 8 + (threadIdx.x >> 5);
    int lane = threadIdx.x & 31;
    const float4* src = reinterpret_cast<const float4*>(cb + (size_t)row * D);
    __nv_bfloat162* dh = reinterpret_cast<__nv_bfloat162*>(g_cbh + (size_t)row * D);
    float s = 0.f;
#pragma unroll
    for (int p = 0; p < 2; ++p) {
        int q = lane + p * 32;
        float4 v = src[q];
        s += v.x * v.x + v.y * v.y + v.z * v.z + v.w * v.w;
        dh[q * 2 + 0] = __nv_bfloat162(__float2bfloat16(v.x), __float2bfloat16(v.y));
        dh[q * 2 + 1] = __nv_bfloat162(__float2bfloat16(v.z), __float2bfloat16(v.w));
    }
#pragma unroll
    for (int o = 16; o > 0; o >>= 1) s += __shfl_xor_sync(0xffffffffu, s, o);
    if (lane == 0) g_cn[row] = s;
}

// ============================================================================
// Kernel 2: projection z = x W^T + b (exact fp32 SIMT, pipelined) + bf16 hi
// split of z. NUMERICS FROZEN (accumulation order = passing rounds).
// ============================================================================
__global__ __launch_bounds__(NTHREADS, 2)
void proj_kernel(const float* __restrict__ x, const float* __restrict__ W,
                 const float* __restrict__ b, float* __restrict__ z) {
    extern __shared__ __align__(16) float psm[];
    const int TS = BK * (BM + 4);          // 2112 floats per tile

    int tid = threadIdx.x;
    int tx = tid & 15, ty = tid >> 4;
    int rowBase = blockIdx.x * BM;
    int colBase = blockIdx.y * BN;

    int r0i = (tid + 0) >> 2, c40 = (tid + 0) & 3;
    int r1i = (tid + 256) >> 2, c41 = (tid + 256) & 3;

    auto gload = [&](float4& vx0, float4& vx1, float4& vw0, float4& vw1, int kt) {
        vx0 = *reinterpret_cast<const float4*>(x + (size_t)(rowBase + r0i) * D + kt * BK + c40 * 4);
        vx1 = *reinterpret_cast<const float4*>(x + (size_t)(rowBase + r1i) * D + kt * BK + c41 * 4);
        vw0 = *reinterpret_cast<const float4*>(W + (size_t)(colBase + r0i) * D + kt * BK + c40 * 4);
        vw1 = *reinterpret_cast<const float4*>(W + (size_t)(colBase + r1i) * D + kt * BK + c41 * 4);
    };
    auto sts = [&](int s, const float4& vx0, const float4& vx1,
                   const float4& vw0, const float4& vw1) {
        float* Xs = psm + s * 2 * TS;
        float* Ws = Xs + TS;
        Xs[(c40 * 4 + 0) * 132 + r0i] = vx0.x;
        Xs[(c40 * 4 + 1) * 132 + r0i] = vx0.y;
        Xs[(c40 * 4 + 2) * 132 + r0i] = vx0.z;
        Xs[(c40 * 4 + 3) * 132 + r0i] = vx0.w;
        Xs[(c41 * 4 + 0) * 132 + r1i] = vx1.x;
        Xs[(c41 * 4 + 1) * 132 + r1i] = vx1.y;
        Xs[(c41 * 4 + 2) * 132 + r1i] = vx1.z;
        Xs[(c41 * 4 + 3) * 132 + r1i] = vx1.w;
        Ws[(c40 * 4 + 0) * 132 + r0i] = vw0.x;
        Ws[(c40 * 4 + 1) * 132 + r0i] = vw0.y;
        Ws[(c40 * 4 + 2) * 132 + r0i] = vw0.z;
        Ws[(c40 * 4 + 3) * 132 + r0i] = vw0.w;
        Ws[(c41 * 4 + 0) * 132 + r1i] = vw1.x;
        Ws[(c41 * 4 + 1) * 132 + r1i] = vw1.y;
        Ws[(c41 * 4 + 2) * 132 + r1i] = vw1.z;
        Ws[(c41 * 4 + 3) * 132 + r1i] = vw1.w;
    };

    float acc[TM][TN];
#pragma unroll
    for (int i = 0; i < TM; ++i)
#pragma unroll
        for (int j = 0; j < TN; ++j) acc[i][j] = 0.f;

    float4 px0, px1, pw0, pw1;
    gload(px0, px1, pw0, pw1, 0);
    sts(0, px0, px1, pw0, pw1);
    __syncthreads();

    for (int kt = 0; kt < D / BK; ++kt) {
        int s = kt & 1;
        if (kt < D / BK - 1) gload(px0, px1, pw0, pw1, kt + 1);
        const float* Xs = psm + s * 2 * TS;
        const float* Ws = Xs + TS;
#pragma unroll
        for (int kk = 0; kk < BK; ++kk) {
            float a[TM], bb[TN];
#pragma unroll
            for (int i = 0; i < TM; ++i) a[i] = Xs[kk * 132 + ty * TM + i];
#pragma unroll
            for (int j = 0; j < TN; ++j) bb[j] = Ws[kk * 132 + tx * TN + j];
#pragma unroll
            for (int i = 0; i < TM; ++i)
#pragma unroll
                for (int j = 0; j < TN; ++j)
                    acc[i][j] = fmaf(a[i], bb[j], acc[i][j]);
        }
        if (kt < D / BK - 1) sts(s ^ 1, px0, px1, pw0, pw1);
        __syncthreads();
    }

    int col0 = colBase + tx * TN;
#pragma unroll
    for (int i = 0; i < TM; ++i) {
        int row = rowBase + ty * TM + i;
        float* zrow = z + (size_t)row * D + col0;
        __nv_bfloat162* hrow = reinterpret_cast<__nv_bfloat162*>(g_zh + (size_t)row * D) + (col0 >> 1);
#pragma unroll
        for (int j4 = 0; j4 < TN / 4; ++j4) {
            float4 v;
            v.x = acc[i][j4 * 4 + 0] + b[col0 + j4 * 4 + 0];
            v.y = acc[i][j4 * 4 + 1] + b[col0 + j4 * 4 + 1];
            v.z = acc[i][j4 * 4 + 2] + b[col0 + j4 * 4 + 2];
            v.w = acc[i][j4 * 4 + 3] + b[col0 + j4 * 4 + 3];
            *reinterpret_cast<float4*>(zrow + j4 * 4) = v;
            hrow[j4 * 2 + 0] = __nv_bfloat162(__float2bfloat16(v.x), __float2bfloat16(v.y));
            hrow[j4 * 2 + 1] = __nv_bfloat162(__float2bfloat16(v.z), __float2bfloat16(v.w));
        }
    }
}

// ============================================================================
// Kernel 3: distance GEMM on HMMA, 1-term (dot = zh.eh), PERSISTENT over n:
// grid (256, 8). Each CTA stages its 128x256 zh tile ONCE into resident smem,
// then loops over 8 code tiles x 4 k-chunks (eh double-buffered, prefetch
// issued pre-compute). Per-128-code-tile top-2 epilogue (harvest unchanged).
// 8 warps 4(m) x 2(n), warp tile 32x64, 2 CTAs/SM.
// ============================================================================
__global__ __launch_bounds__(256, 2)
void dist_mma_kernel(int Kcodes) {
    extern __shared__ __align__(16) char smem[];
    const uint32_t smBase = smem_to_u32(smem);

    const int tid = threadIdx.x, lane = tid & 31, wid = tid >> 5;
    const int wm = wid >> 1, wn = wid & 1;        // 4 x 2 warp grid
    const int rowBase = blockIdx.x * 128;
    const int ntBase = blockIdx.y * 8;            // 8 code tiles per CTA

    const int q = lane >> 3, i8 = lane & 7;
    // A-frag base within resident zh (k16 offset added per use: kk*32 bytes)
    const uint32_t aOff = (uint32_t)(((wm * 32 + (q & 1) * 8 + i8) * ZSB + (q >> 1) * 8) * 2);
    // B-frag base within an eh stage
    const uint32_t bOff = (uint32_t)(((wn * 64 + (q >> 1) * 8 + i8) * ESB + (q & 1) * 8) * 2);

    float acc[2][8][4];
#pragma unroll
    for (int mt = 0; mt < 2; ++mt)
#pragma unroll
        for (int nt = 0; nt < 8; ++nt)
#pragma unroll
            for (int e = 0; e < 4; ++e) acc[mt][nt][e] = 0.f;

    // ---- stage resident zh: 4096 x 16B chunks, 16 per thread ----
    {
#pragma unroll
        for (int i = 0; i < 16; ++i) {
            int c = tid + i * 256;
            int row = c >> 5, hf = c & 31;
            cp16(smBase + (uint32_t)(row * (ZSB * 2) + hf * 16),
                 g_zh + (size_t)(rowBase + row) * D + hf * 8);
        }
        asm volatile("cp.async.commit_group;" ::: "memory");
    }

    // ---- eh chunk stager: chunk c = (tile c>>2, kchunk c&3), 4 cp16/thread ----
    auto stage_e = [&](int buf, int c) {
        int nt = ntBase + (c >> 2);
        int kc = (c & 3) * 64;
        uint32_t base = smBase + EOFF + (uint32_t)buf * ETILEB;
#pragma unroll
        for (int i = 0; i < 4; ++i) {
            int cc = tid + i * 256;             // 0..1023
            int hf = cc & 7;
            int r = cc >> 3;
            cp16(base + (uint32_t)(r * (ESB * 2) + hf * 16),
                 g_cbh + (size_t)(nt * 128 + r) * D + kc + hf * 8);
        }
        asm volatile("cp.async.commit_group;" ::: "memory");
    };

    auto load_frags = [&](uint32_t* ah, uint32_t (*bfr)[2], uint32_t eb, int kk, int kh) {
#pragma unroll
        for (int mt = 0; mt < 2; ++mt)
            ldsm_x4(ah[mt * 4 + 0], ah[mt * 4 + 1], ah[mt * 4 + 2], ah[mt * 4 + 3],
                    smBase + aOff + (uint32_t)(mt * 16 * ZSB * 2 + kk * 32));
#pragma unroll
        for (int nt2 = 0; nt2 < 4; ++nt2) {
            uint32_t r0, r1, r2, r3;
            ldsm_x4(r0, r1, r2, r3,
                    eb + bOff + (uint32_t)(nt2 * 16 * ESB * 2 + kh * 32));
            bfr[nt2 * 2 + 0][0] = r0; bfr[nt2 * 2 + 0][1] = r1;
            bfr[nt2 * 2 + 1][0] = r2; bfr[nt2 * 2 + 1][1] = r3;
        }
    };

    auto mma_all = [&](uint32_t* ah, uint32_t (*bfr)[2]) {
#pragma unroll
        for (int mt = 0; mt < 2; ++mt)
#pragma unroll
            for (int nt = 0; nt < 8; ++nt)
                mma16816(acc[mt][nt], ah[mt * 4 + 0], ah[mt * 4 + 1],
                         ah[mt * 4 + 2], ah[mt * 4 + 3],
                         bfr[nt][0], bfr[nt][1]);
    };

    float4 (*red)[2] = reinterpret_cast<float4(*)[2]>(smem + REDOFF);

    // prologue: zh + chunk0 resident, published
    stage_e(0, 0);
    asm volatile("cp.async.wait_group 0;" ::: "memory");
    __syncthreads();

    uint32_t ahF[2][8];
    uint32_t bfF[2][8][2];

    for (int c = 0; c < 32; ++c) {
        // prefetch next chunk into the other buffer (its last readers retired
        // by the wait+barrier at the end of iteration c-1)
        if (c + 1 < 32) stage_e((c + 1) & 1, c + 1);

        int kt = c & 3;
        uint32_t eb = smBase + EOFF + (uint32_t)(c & 1) * ETILEB;

        load_frags(ahF[0], bfF[0], eb, kt * 4 + 0, 0);
        load_frags(ahF[1], bfF[1], eb, kt * 4 + 1, 1);  mma_all(ahF[0], bfF[0]);
        load_frags(ahF[0], bfF[0], eb, kt * 4 + 2, 2);  mma_all(ahF[1], bfF[1]);
        load_frags(ahF[1], bfF[1], eb, kt * 4 + 3, 3);  mma_all(ahF[0], bfF[0]);
        mma_all(ahF[1], bfF[1]);

        // ---- per-tile epilogue at the last k-chunk of each code tile ----
        if (kt == 3) {
            int ntG = ntBase + (c >> 2);
            int codeBase = ntG * 128;
            const int g = lane >> 2;
            const int cb0 = codeBase + wn * 64 + (lane & 3) * 2;
            float cn8[8][2];
#pragma unroll
            for (int nt = 0; nt < 8; ++nt) {
                cn8[nt][0] = __ldg(&g_cn[cb0 + nt * 8 + 0]);
                cn8[nt][1] = __ldg(&g_cn[cb0 + nt * 8 + 1]);
            }
#pragma unroll
            for (int mt = 0; mt < 2; ++mt)
#pragma unroll
                for (int h = 0; h < 2; ++h) {
                    float v0 = CUDART_INF_F, v1 = CUDART_INF_F;
                    int i0 = 0, i1 = 0;
#pragma unroll
                    for (int nt = 0; nt < 8; ++nt)
#pragma unroll
                        for (int e = 0; e < 2; ++e) {
                            float dd = fmaf(-2.f, acc[mt][nt][h * 2 + e], cn8[nt][e]);
                            int code = cb0 + nt * 8 + e;
                            if (dd < v0) { v1 = v0; i1 = i0; v0 = dd; i0 = code; }
                            else if (dd < v1) { v1 = dd; i1 = code; }
                        }
#pragma unroll
                    for (int off = 1; off <= 2; off <<= 1) {
                        float w0 = __shfl_xor_sync(0xffffffffu, v0, off);
                        float w1 = __shfl_xor_sync(0xffffffffu, v1, off);
                        int j0 = __shfl_xor_sync(0xffffffffu, i0, off);
                        int j1 = __shfl_xor_sync(0xffffffffu, i1, off);
                        top2_merge(v0, i0, v1, i1, w0, j0, w1, j1);
                    }
                    if ((lane & 3) == 0)
                        red[wm * 32 + mt * 16 + h * 8 + g][wn] =
                            make_float4(v0, __int_as_float(i0), v1, __int_as_float(i1));
                }
            __syncthreads();
            if (tid < 128) {
                float4 p0 = red[tid][0];
                float4 p1 = red[tid][1];
                float v0 = p0.x, v1 = p0.z;
                int i0 = __float_as_int(p0.y), i1 = __float_as_int(p0.w);
                top2_merge(v0, i0, v1, i1, p1.x, __float_as_int(p1.y),
                           p1.z, __float_as_int(p1.w));
                size_t slot = (size_t)(rowBase + tid) * NTILE + ntG;
                g_cv[slot] = make_float2(v0, v1);
                g_ci[slot] = make_int2(i0, i1);
            }
            // reset accumulators for the next code tile
#pragma unroll
            for (int mt = 0; mt < 2; ++mt)
#pragma unroll
                for (int nt = 0; nt < 8; ++nt)
#pragma unroll
                    for (int e = 0; e < 4; ++e) acc[mt][nt][e] = 0.f;
        }

        // publish chunk c+1; retire all reads of chunk c's buffer
        if (c + 1 < 32) {
            asm volatile("cp.async.wait_group 0;" ::: "memory");
            __syncthreads();
        }
    }
}

// ============================================================================
// Kernel 4 (fused): per-row approx top-4 + exact fp32 rescore + gather q into
// out + elementwise loss partial. One warp per row; 8 rows per block.
// ============================================================================
__global__ __launch_bounds__(256)
void rescore_gather_kernel(float* __restrict__ out,
                           const float* __restrict__ cb, int NT) {
    __shared__ float wloss[8];
    int warp = threadIdx.x >> 5;
    int row = blockIdx.x * 8 + warp;
    int lane = threadIdx.x & 31;

    float vv[4] = { CUDART_INF_F, CUDART_INF_F, CUDART_INF_F, CUDART_INF_F };
    int ii[4] = { 0x7fffffff, 0x7fffffff, 0x7fffffff, 0x7fffffff };
    if (lane < NT) {
        float2 cv = g_cv[(size_t)row * NT + lane];
        int2 ci = g_ci[(size_t)row * NT + lane];
        vv[0] = cv.x; ii[0] = ci.x;
        vv[1] = cv.y; ii[1] = ci.y;
    }
    if (lane + 32 < NT) {
        float2 cv = g_cv[(size_t)row * NT + lane + 32];
        int2 ci = g_ci[(size_t)row * NT + lane + 32];
        vv[2] = cv.x; ii[2] = ci.x;
        vv[3] = cv.y; ii[3] = ci.y;
    }

    int jj[4];
#pragma unroll
    for (int r = 0; r < 4; ++r) {
        float bv = CUDART_INF_F; int bi = 0x7fffffff;
#pragma unroll
        for (int k = 0; k < 4; ++k)
            if (vv[k] < bv || (vv[k] == bv && ii[k] < bi)) { bv = vv[k]; bi = ii[k]; }
#pragma unroll
        for (int off = 16; off > 0; off >>= 1) {
            float wv = __shfl_xor_sync(0xffffffffu, bv, off);
            int wi = __shfl_xor_sync(0xffffffffu, bi, off);
            if (wv < bv || (wv == bv && wi < bi)) { bv = wv; bi = wi; }
        }
        jj[r] = (bi == 0x7fffffff) ? 0 : bi;
#pragma unroll
        for (int k = 0; k < 4; ++k)
            if (ii[k] == bi) { vv[k] = CUDART_INF_F; ii[k] = 0x7fffffff; }
    }

    float4* zr = reinterpret_cast<float4*>(out + (size_t)row * D);
    float4 z0 = zr[lane], z1 = zr[lane + 32];
    float s4[4];
#pragma unroll
    for (int j = 0; j < 4; ++j) {
        const float4* ej = reinterpret_cast<const float4*>(cb + (size_t)jj[j] * D);
        float4 a = ej[lane];
        float4 c = ej[lane + 32];
        float s = 0.f;
        s = fmaf(z0.x, a.x, s); s = fmaf(z0.y, a.y, s);
        s = fmaf(z0.z, a.z, s); s = fmaf(z0.w, a.w, s);
        s = fmaf(z1.x, c.x, s); s = fmaf(z1.y, c.y, s);
        s = fmaf(z1.z, c.z, s); s = fmaf(z1.w, c.w, s);
        s4[j] = s;
    }
#pragma unroll
    for (int off = 16; off > 0; off >>= 1) {
#pragma unroll
        for (int j = 0; j < 4; ++j)
            s4[j] += __shfl_xor_sync(0xffffffffu, s4[j], off);
    }
    float best = CUDART_INF_F; int bi = 0x7fffffff;
#pragma unroll
    for (int j = 0; j < 4; ++j) {
        float dj = g_cn[jj[j]] - 2.f * s4[j];
        if (dj < best || (dj == best && jj[j] < bi)) { best = dj; bi = jj[j]; }
    }

    const float4* ew = reinterpret_cast<const float4*>(cb + (size_t)bi * D);
    float ls = 0.f;
    {
        float4 qv = ew[lane];
        zr[lane] = qv;
        float dx = z0.x - qv.x, dy = z0.y - qv.y;
        float dz = z0.z - qv.z, dw = z0.w - qv.w;
        ls += dx * dx + dy * dy + dz * dz + dw * dw;
        qv = ew[lane + 32];
        zr[lane + 32] = qv;
        dx = z1.x - qv.x; dy = z1.y - qv.y;
        dz = z1.z - qv.z; dw = z1.w - qv.w;
        ls += dx * dx + dy * dy + dz * dz + dw * dw;
    }
#pragma unroll
    for (int off = 16; off > 0; off >>= 1)
        ls += __shfl_xor_sync(0xffffffffu, ls, off);
    if (lane == 0) wloss[warp] = ls;
    __syncthreads();
    if (threadIdx.x == 0) {
        float t = 0.f;
#pragma unroll
        for (int w = 0; w < 8; ++w) t += wloss[w];
        g_part[blockIdx.x] = t;
    }
}

// ============================================================================
// Kernel 5: finalize losses (4096 partials, deterministic tree)
// ============================================================================
__global__ __launch_bounds__(1024)
void finalize_kernel(float* __restrict__ out, int out_size, float inv_count) {
    __shared__ float sr[1024];
    int t = threadIdx.x;
    float s = 0.f;
#pragma unroll
    for (int p = 0; p < 4; ++p) s += g_part[t + p * 1024];
    sr[t] = s;
    __syncthreads();
    for (int st = 512; st > 0; st >>= 1) {
        if (t < st) sr[t] += sr[t + st];
        __syncthreads();
    }
    if (t == 0) {
        float m = sr[0] * inv_count;
        out[out_size - 2] = m;
        out[out_size - 1] = m;
    }
}

// ============================================================================
extern "C" void kernel_launch(void* const* d_in, const int* in_sizes, int n_in,
                              void* d_out, int out_size) {
    const float* x  = (const float*)d_in[0];
    const float* W  = (const float*)d_in[1];
    const float* b  = (const float*)d_in[2];
    const float* cb = (const float*)d_in[3];

    int M      = in_sizes[0] / D;   // 32768
    int Kcodes = in_sizes[3] / D;   // 8192
    int NT     = Kcodes / 128;      // 64
    float* out = (float*)d_out;

    cudaFuncSetAttribute(dist_mma_kernel,
                         cudaFuncAttributeMaxDynamicSharedMemorySize, DIST_SMEM);
    cudaFuncSetAttribute(proj_kernel,
                         cudaFuncAttributeMaxDynamicSharedMemorySize, PROJ_SMEM);

    // 1. fused codebook norms + bf16 hi split
    cnsplit_kernel<<<Kcodes / 8, 256>>>(cb);

    // 2. projection (exact fp32 z into out, plus bf16 hi of z), pipelined
    dim3 pg(M / BM, D / BN);
    proj_kernel<<<pg, NTHREADS, PROJ_SMEM>>>(x, W, b, out);

    // 3. HMMA distance GEMM, persistent over 8 code tiles per CTA
    dist_mma_kernel<<<dim3(M / 128, NT / 8), 256, DIST_SMEM>>>(Kcodes);

    // 4. fused top-4 select + exact rescore + gather + loss partials
    rescore_gather_kernel<<<M / 8, 256>>>(out, cb, NT);

    // 5. finalize
    finalize_kernel<<<1, 1024>>>(out, out_size, 1.0f / (float)(M * D));
}

// round 14
// speedup vs baseline: 1.0355x; 1.0355x over previous
#include <cuda_runtime.h>
#include <cuda_bf16.h>
#include <math_constants.h>
#include <cstdint>

// ============================================================================
// Problem constants
// ============================================================================
#define D        256
#define MROWS    32768
#define KCODES   8192
#define NTILE    64            // KCODES / 128
#define BM       128
#define BN       128
#define BK       16
#define TM       8
#define TN       8
#define NTHREADS 256

// dist kernel smem geometry (BK = 64, 2 tiles per stage: zh, eh; 3-stage ring)
#define SB       72                    // bf16 row stride (144 B, ldsm conflict-free)
#define TILEB    (128 * SB * 2)        // 18432 B per 128x64 tile
#define STAGEB   (2 * TILEB)           // zh + eh = 36864 B per stage
#define NSTAGE   3
#define DIST_SMEM (NSTAGE * STAGEB)    // 110592 B -> 2 CTAs/SM

// proj kernel smem: 2 stages x 2 tiles x 16 x 132 floats
#define PROJ_SMEM (2 * 2 * BK * (BM + 4) * 4)   // 67584 B

// ============================================================================
// Device scratch (no cudaMalloc allowed)
// ============================================================================
__device__ float          g_cn[KCODES];
__device__ float          g_part[4096];
__device__ __nv_bfloat16  g_cbh[KCODES * D];
__device__ __nv_bfloat16  g_zh[MROWS * D];
__device__ float2         g_cv[(size_t)MROWS * NTILE];
__device__ int2           g_ci[(size_t)MROWS * NTILE];

// ============================================================================
// Helpers
// ============================================================================
__device__ __forceinline__ uint32_t smem_to_u32(const void* p) {
    uint32_t a;
    asm("{ .reg .u64 t; cvta.to.shared.u64 t, %1; cvt.u32.u64 %0, t; }"
        : "=r"(a) : "l"(p));
    return a;
}
__device__ __forceinline__ void cp16(uint32_t dst, const void* src) {
    asm volatile("cp.async.cg.shared.global [%0], [%1], 16;"
        :: "r"(dst), "l"(__cvta_generic_to_global(src)) : "memory");
}
__device__ __forceinline__ void ldsm_x4(uint32_t& r0, uint32_t& r1,
                                        uint32_t& r2, uint32_t& r3, uint32_t addr) {
    asm volatile("ldmatrix.sync.aligned.m8n8.x4.shared.b16 {%0,%1,%2,%3}, [%4];"
        : "=r"(r0), "=r"(r1), "=r"(r2), "=r"(r3) : "r"(addr));
}
__device__ __forceinline__ void mma16816(float* c, uint32_t a0, uint32_t a1,
                                         uint32_t a2, uint32_t a3,
                                         uint32_t b0, uint32_t b1) {
    asm volatile("mma.sync.aligned.m16n8k16.row.col.f32.bf16.bf16.f32 "
        "{%0,%1,%2,%3}, {%4,%5,%6,%7}, {%8,%9}, {%0,%1,%2,%3};"
        : "+f"(c[0]), "+f"(c[1]), "+f"(c[2]), "+f"(c[3])
        : "r"(a0), "r"(a1), "r"(a2), "r"(a3), "r"(b0), "r"(b1));
}
__device__ __forceinline__ void top2_merge(float& v0, int& i0, float& v1, int& i1,
                                           float w0, int j0, float w1, int j1) {
    if (w0 < v0) {
        if (v0 < w1) { v1 = v0; i1 = i0; } else { v1 = w1; i1 = j1; }
        v0 = w0; i0 = j0;
    } else if (w0 < v1) { v1 = w0; i1 = j0; }
}

// ============================================================================
// Kernel 1: fused codebook norms + bf16 hi-split (one pass over cb)
// ============================================================================
__global__ __launch_bounds__(256)
void cnsplit_kernel(const float* __restrict__ cb) {
    int row = blockIdx.x * 8 + (threadIdx.x >> 5);
    int lane = threadIdx.x & 31;
    const float4* src = reinterpret_cast<const float4*>(cb + (size_t)row * D);
    __nv_bfloat162* dh = reinterpret_cast<__nv_bfloat162*>(g_cbh + (size_t)row * D);
    float s = 0.f;
#pragma unroll
    for (int p = 0; p < 2; ++p) {
        int q = lane + p * 32;
        float4 v = src[q];
        s += v.x * v.x + v.y * v.y + v.z * v.z + v.w * v.w;
        dh[q * 2 + 0] = __nv_bfloat162(__float2bfloat16(v.x), __float2bfloat16(v.y));
        dh[q * 2 + 1] = __nv_bfloat162(__float2bfloat16(v.z), __float2bfloat16(v.w));
    }
#pragma unroll
    for (int o = 16; o > 0; o >>= 1) s += __shfl_xor_sync(0xffffffffu, s, o);
    if (lane == 0) g_cn[row] = s;
}

// ============================================================================
// Kernel 2: projection z = x W^T + b (exact fp32 SIMT, pipelined) + bf16 hi
// split of z. NUMERICS FROZEN (accumulation order = passing rounds).
// ============================================================================
__global__ __launch_bounds__(NTHREADS, 2)
void proj_kernel(const float* __restrict__ x, const float* __restrict__ W,
                 const float* __restrict__ b, float* __restrict__ z) {
    extern __shared__ __align__(16) float psm[];
    const int TS = BK * (BM + 4);          // 2112 floats per tile

    int tid = threadIdx.x;
    int tx = tid & 15, ty = tid >> 4;
    int rowBase = blockIdx.x * BM;
    int colBase = blockIdx.y * BN;

    int r0i = (tid + 0) >> 2, c40 = (tid + 0) & 3;
    int r1i = (tid + 256) >> 2, c41 = (tid + 256) & 3;

    auto gload = [&](float4& vx0, float4& vx1, float4& vw0, float4& vw1, int kt) {
        vx0 = *reinterpret_cast<const float4*>(x + (size_t)(rowBase + r0i) * D + kt * BK + c40 * 4);
        vx1 = *reinterpret_cast<const float4*>(x + (size_t)(rowBase + r1i) * D + kt * BK + c41 * 4);
        vw0 = *reinterpret_cast<const float4*>(W + (size_t)(colBase + r0i) * D + kt * BK + c40 * 4);
        vw1 = *reinterpret_cast<const float4*>(W + (size_t)(colBase + r1i) * D + kt * BK + c41 * 4);
    };
    auto sts = [&](int s, const float4& vx0, const float4& vx1,
                   const float4& vw0, const float4& vw1) {
        float* Xs = psm + s * 2 * TS;
        float* Ws = Xs + TS;
        Xs[(c40 * 4 + 0) * 132 + r0i] = vx0.x;
        Xs[(c40 * 4 + 1) * 132 + r0i] = vx0.y;
        Xs[(c40 * 4 + 2) * 132 + r0i] = vx0.z;
        Xs[(c40 * 4 + 3) * 132 + r0i] = vx0.w;
        Xs[(c41 * 4 + 0) * 132 + r1i] = vx1.x;
        Xs[(c41 * 4 + 1) * 132 + r1i] = vx1.y;
        Xs[(c41 * 4 + 2) * 132 + r1i] = vx1.z;
        Xs[(c41 * 4 + 3) * 132 + r1i] = vx1.w;
        Ws[(c40 * 4 + 0) * 132 + r0i] = vw0.x;
        Ws[(c40 * 4 + 1) * 132 + r0i] = vw0.y;
        Ws[(c40 * 4 + 2) * 132 + r0i] = vw0.z;
        Ws[(c40 * 4 + 3) * 132 + r0i] = vw0.w;
        Ws[(c41 * 4 + 0) * 132 + r1i] = vw1.x;
        Ws[(c41 * 4 + 1) * 132 + r1i] = vw1.y;
        Ws[(c41 * 4 + 2) * 132 + r1i] = vw1.z;
        Ws[(c41 * 4 + 3) * 132 + r1i] = vw1.w;
    };

    float acc[TM][TN];
#pragma unroll
    for (int i = 0; i < TM; ++i)
#pragma unroll
        for (int j = 0; j < TN; ++j) acc[i][j] = 0.f;

    float4 px0, px1, pw0, pw1;
    gload(px0, px1, pw0, pw1, 0);
    sts(0, px0, px1, pw0, pw1);
    __syncthreads();

    for (int kt = 0; kt < D / BK; ++kt) {
        int s = kt & 1;
        if (kt < D / BK - 1) gload(px0, px1, pw0, pw1, kt + 1);
        const float* Xs = psm + s * 2 * TS;
        const float* Ws = Xs + TS;
#pragma unroll
        for (int kk = 0; kk < BK; ++kk) {
            float a[TM], bb[TN];
#pragma unroll
            for (int i = 0; i < TM; ++i) a[i] = Xs[kk * 132 + ty * TM + i];
#pragma unroll
            for (int j = 0; j < TN; ++j) bb[j] = Ws[kk * 132 + tx * TN + j];
#pragma unroll
            for (int i = 0; i < TM; ++i)
#pragma unroll
                for (int j = 0; j < TN; ++j)
                    acc[i][j] = fmaf(a[i], bb[j], acc[i][j]);
        }
        if (kt < D / BK - 1) sts(s ^ 1, px0, px1, pw0, pw1);
        __syncthreads();
    }

    int col0 = colBase + tx * TN;
#pragma unroll
    for (int i = 0; i < TM; ++i) {
        int row = rowBase + ty * TM + i;
        float* zrow = z + (size_t)row * D + col0;
        __nv_bfloat162* hrow = reinterpret_cast<__nv_bfloat162*>(g_zh + (size_t)row * D) + (col0 >> 1);
#pragma unroll
        for (int j4 = 0; j4 < TN / 4; ++j4) {
            float4 v;
            v.x = acc[i][j4 * 4 + 0] + b[col0 + j4 * 4 + 0];
            v.y = acc[i][j4 * 4 + 1] + b[col0 + j4 * 4 + 1];
            v.z = acc[i][j4 * 4 + 2] + b[col0 + j4 * 4 + 2];
            v.w = acc[i][j4 * 4 + 3] + b[col0 + j4 * 4 + 3];
            *reinterpret_cast<float4*>(zrow + j4 * 4) = v;
            hrow[j4 * 2 + 0] = __nv_bfloat162(__float2bfloat16(v.x), __float2bfloat16(v.y));
            hrow[j4 * 2 + 1] = __nv_bfloat162(__float2bfloat16(v.z), __float2bfloat16(v.w));
        }
    }
}

// ============================================================================
// Kernel 3: distance GEMM on HMMA, 1-term (dot = zh.eh).
// R12 configuration — the measured optimum of this design space:
// CTA 128x128, 8 warps 4(m) x 2(n), warp tile 32x64, 2 CTAs/SM.
// BK=64, 3-stage ring, wait_group 1 prefetch depth, intra-kt fragment
// double buffering, single barrier per k-chunk.
// ============================================================================
__global__ __launch_bounds__(256, 2)
void dist_mma_kernel(int Kcodes) {
    extern __shared__ __align__(16) char smem[];
    const uint32_t smBase = smem_to_u32(smem);

    const int tid = threadIdx.x, lane = tid & 31, wid = tid >> 5;
    const int wm = wid >> 1, wn = wid & 1;        // 4 x 2 warp grid
    const int rowBase = blockIdx.x * 128;
    const int codeBase = blockIdx.y * 128;

    const int q = lane >> 3, i8 = lane & 7;
    const uint32_t aOff = (uint32_t)(((wm * 32 + (q & 1) * 8 + i8) * SB + (q >> 1) * 8) * 2);
    const uint32_t bOff = (uint32_t)(((wn * 64 + (q >> 1) * 8 + i8) * SB + (q & 1) * 8) * 2);

    float acc[2][8][4];
#pragma unroll
    for (int mt = 0; mt < 2; ++mt)
#pragma unroll
        for (int nt = 0; nt < 8; ++nt)
#pragma unroll
            for (int e = 0; e < 4; ++e) acc[mt][nt][e] = 0.f;

    auto stage = [&](int buf, int kt) {
        uint32_t base = smBase + (uint32_t)buf * STAGEB;
        int kc = kt * 64;
#pragma unroll
        for (int i = 0; i < 8; ++i) {
            int c = tid + i * 256;              // 0..2047
            int hf = c & 7;
            int r = (c >> 3) & 127;
            int tile = c >> 10;                 // 0=zh, 1=eh
            const __nv_bfloat16* src = (tile == 0) ? g_zh : g_cbh;
            int gr = (tile == 0) ? (rowBase + r) : (codeBase + r);
            cp16(base + (uint32_t)(tile * TILEB + r * (SB * 2) + hf * 16),
                 src + (size_t)gr * D + kc + hf * 8);
        }
        asm volatile("cp.async.commit_group;" ::: "memory");
    };

    auto load_frags = [&](uint32_t* ah, uint32_t (*bfr)[2], uint32_t tb, int kh) {
#pragma unroll
        for (int mt = 0; mt < 2; ++mt)
            ldsm_x4(ah[mt * 4 + 0], ah[mt * 4 + 1], ah[mt * 4 + 2], ah[mt * 4 + 3],
                    tb + aOff + (uint32_t)(mt * 16 * SB * 2 + kh * 32));
#pragma unroll
        for (int nt2 = 0; nt2 < 4; ++nt2) {
            uint32_t r0, r1, r2, r3;
            ldsm_x4(r0, r1, r2, r3,
                    tb + TILEB + bOff + (uint32_t)(nt2 * 16 * SB * 2 + kh * 32));
            bfr[nt2 * 2 + 0][0] = r0; bfr[nt2 * 2 + 0][1] = r1;
            bfr[nt2 * 2 + 1][0] = r2; bfr[nt2 * 2 + 1][1] = r3;
        }
    };

    auto mma_all = [&](uint32_t* ah, uint32_t (*bfr)[2]) {
#pragma unroll
        for (int mt = 0; mt < 2; ++mt)
#pragma unroll
            for (int nt = 0; nt < 8; ++nt)
                mma16816(acc[mt][nt], ah[mt * 4 + 0], ah[mt * 4 + 1],
                         ah[mt * 4 + 2], ah[mt * 4 + 3],
                         bfr[nt][0], bfr[nt][1]);
    };

    // prologue: commit stage(0), stage(1)
    stage(0, 0); stage(1, 1);

    uint32_t ahF[2][8];
    uint32_t bfF[2][8][2];

#pragma unroll
    for (int kt = 0; kt < 4; ++kt) {
        if (kt < 3) asm volatile("cp.async.wait_group 1;" ::: "memory");
        else        asm volatile("cp.async.wait_group 0;" ::: "memory");
        __syncthreads();                 // publish buffer kt; retire reads of buf (kt+2)%3
        if (kt < 2) stage((kt + 2) % 3, kt + 2);

        uint32_t tb = smBase + (uint32_t)(kt % 3) * STAGEB;

        load_frags(ahF[0], bfF[0], tb, 0);
        load_frags(ahF[1], bfF[1], tb, 1);  mma_all(ahF[0], bfF[0]);
        load_frags(ahF[0], bfF[0], tb, 2);  mma_all(ahF[1], bfF[1]);
        load_frags(ahF[1], bfF[1], tb, 3);  mma_all(ahF[0], bfF[0]);
        mma_all(ahF[1], bfF[1]);
    }

    // ---- epilogue: d = cn - 2*dot, per-row top-2 over this CTA's 128 codes ----
    __syncthreads();                      // mainloop smem dead; alias as red[]
    float4 (*red)[2] = reinterpret_cast<float4(*)[2]>(smem);

    const int g = lane >> 2;
    const int cb0 = codeBase + wn * 64 + (lane & 3) * 2;
    float cn8[8][2];
#pragma unroll
    for (int nt = 0; nt < 8; ++nt) {
        cn8[nt][0] = __ldg(&g_cn[cb0 + nt * 8 + 0]);
        cn8[nt][1] = __ldg(&g_cn[cb0 + nt * 8 + 1]);
    }
#pragma unroll
    for (int mt = 0; mt < 2; ++mt)
#pragma unroll
        for (int h = 0; h < 2; ++h) {
            float v0 = CUDART_INF_F, v1 = CUDART_INF_F;
            int i0 = 0, i1 = 0;
#pragma unroll
            for (int nt = 0; nt < 8; ++nt)
#pragma unroll
                for (int e = 0; e < 2; ++e) {
                    float dd = fmaf(-2.f, acc[mt][nt][h * 2 + e], cn8[nt][e]);
                    int code = cb0 + nt * 8 + e;
                    if (dd < v0) { v1 = v0; i1 = i0; v0 = dd; i0 = code; }
                    else if (dd < v1) { v1 = dd; i1 = code; }
                }
#pragma unroll
            for (int off = 1; off <= 2; off <<= 1) {
                float w0 = __shfl_xor_sync(0xffffffffu, v0, off);
                float w1 = __shfl_xor_sync(0xffffffffu, v1, off);
                int j0 = __shfl_xor_sync(0xffffffffu, i0, off);
                int j1 = __shfl_xor_sync(0xffffffffu, i1, off);
                top2_merge(v0, i0, v1, i1, w0, j0, w1, j1);
            }
            if ((lane & 3) == 0)
                red[wm * 32 + mt * 16 + h * 8 + g][wn] =
                    make_float4(v0, __int_as_float(i0), v1, __int_as_float(i1));
        }
    __syncthreads();

    if (tid < 128) {
        float4 p0 = red[tid][0];
        float4 p1 = red[tid][1];
        float v0 = p0.x, v1 = p0.z;
        int i0 = __float_as_int(p0.y), i1 = __float_as_int(p0.w);
        top2_merge(v0, i0, v1, i1, p1.x, __float_as_int(p1.y), p1.z, __float_as_int(p1.w));
        size_t slot = (size_t)(rowBase + tid) * gridDim.y + blockIdx.y;
        g_cv[slot] = make_float2(v0, v1);
        g_ci[slot] = make_int2(i0, i1);
    }
}

// ============================================================================
// Kernel 4 (fused): per-row approx top-4 + exact fp32 rescore + gather q into
// out + elementwise loss partial. One warp per row; 8 rows per block.
// ============================================================================
__global__ __launch_bounds__(256)
void rescore_gather_kernel(float* __restrict__ out,
                           const float* __restrict__ cb, int NT) {
    __shared__ float wloss[8];
    int warp = threadIdx.x >> 5;
    int row = blockIdx.x * 8 + warp;
    int lane = threadIdx.x & 31;

    float vv[4] = { CUDART_INF_F, CUDART_INF_F, CUDART_INF_F, CUDART_INF_F };
    int ii[4] = { 0x7fffffff, 0x7fffffff, 0x7fffffff, 0x7fffffff };
    if (lane < NT) {
        float2 cv = g_cv[(size_t)row * NT + lane];
        int2 ci = g_ci[(size_t)row * NT + lane];
        vv[0] = cv.x; ii[0] = ci.x;
        vv[1] = cv.y; ii[1] = ci.y;
    }
    if (lane + 32 < NT) {
        float2 cv = g_cv[(size_t)row * NT + lane + 32];
        int2 ci = g_ci[(size_t)row * NT + lane + 32];
        vv[2] = cv.x; ii[2] = ci.x;
        vv[3] = cv.y; ii[3] = ci.y;
    }

    // select approx top-4 (4 rounds of global argmin with consumption)
    int jj[4];
#pragma unroll
    for (int r = 0; r < 4; ++r) {
        float bv = CUDART_INF_F; int bi = 0x7fffffff;
#pragma unroll
        for (int k = 0; k < 4; ++k)
            if (vv[k] < bv || (vv[k] == bv && ii[k] < bi)) { bv = vv[k]; bi = ii[k]; }
#pragma unroll
        for (int off = 16; off > 0; off >>= 1) {
            float wv = __shfl_xor_sync(0xffffffffu, bv, off);
            int wi = __shfl_xor_sync(0xffffffffu, bi, off);
            if (wv < bv || (wv == bv && wi < bi)) { bv = wv; bi = wi; }
        }
        jj[r] = (bi == 0x7fffffff) ? 0 : bi;
#pragma unroll
        for (int k = 0; k < 4; ++k)
            if (ii[k] == bi) { vv[k] = CUDART_INF_F; ii[k] = 0x7fffffff; }
    }

    // exact fp32 rescore of 4 candidates: d_j = cn[j] - 2 * z.e_j
    float4* zr = reinterpret_cast<float4*>(out + (size_t)row * D);
    float4 z0 = zr[lane], z1 = zr[lane + 32];
    float s4[4];
#pragma unroll
    for (int j = 0; j < 4; ++j) {
        const float4* ej = reinterpret_cast<const float4*>(cb + (size_t)jj[j] * D);
        float4 a = ej[lane];
        float4 c = ej[lane + 32];
        float s = 0.f;
        s = fmaf(z0.x, a.x, s); s = fmaf(z0.y, a.y, s);
        s = fmaf(z0.z, a.z, s); s = fmaf(z0.w, a.w, s);
        s = fmaf(z1.x, c.x, s); s = fmaf(z1.y, c.y, s);
        s = fmaf(z1.z, c.z, s); s = fmaf(z1.w, c.w, s);
        s4[j] = s;
    }
#pragma unroll
    for (int off = 16; off > 0; off >>= 1) {
#pragma unroll
        for (int j = 0; j < 4; ++j)
            s4[j] += __shfl_xor_sync(0xffffffffu, s4[j], off);
    }
    float best = CUDART_INF_F; int bi = 0x7fffffff;
#pragma unroll
    for (int j = 0; j < 4; ++j) {
        float dj = g_cn[jj[j]] - 2.f * s4[j];
        if (dj < best || (dj == best && jj[j] < bi)) { best = dj; bi = jj[j]; }
    }

    // gather q, write x_recon row (= q), accumulate elementwise loss
    const float4* ew = reinterpret_cast<const float4*>(cb + (size_t)bi * D);
    float ls = 0.f;
    {
        float4 qv = ew[lane];
        zr[lane] = qv;
        float dx = z0.x - qv.x, dy = z0.y - qv.y;
        float dz = z0.z - qv.z, dw = z0.w - qv.w;
        ls += dx * dx + dy * dy + dz * dz + dw * dw;
        qv = ew[lane + 32];
        zr[lane + 32] = qv;
        dx = z1.x - qv.x; dy = z1.y - qv.y;
        dz = z1.z - qv.z; dw = z1.w - qv.w;
        ls += dx * dx + dy * dy + dz * dz + dw * dw;
    }
#pragma unroll
    for (int off = 16; off > 0; off >>= 1)
        ls += __shfl_xor_sync(0xffffffffu, ls, off);
    if (lane == 0) wloss[warp] = ls;
    __syncthreads();
    if (threadIdx.x == 0) {
        float t = 0.f;
#pragma unroll
        for (int w = 0; w < 8; ++w) t += wloss[w];
        g_part[blockIdx.x] = t;
    }
}

// ============================================================================
// Kernel 5: finalize losses (4096 partials, deterministic tree)
// ============================================================================
__global__ __launch_bounds__(1024)
void finalize_kernel(float* __restrict__ out, int out_size, float inv_count) {
    __shared__ float sr[1024];
    int t = threadIdx.x;
    float s = 0.f;
#pragma unroll
    for (int p = 0; p < 4; ++p) s += g_part[t + p * 1024];
    sr[t] = s;
    __syncthreads();
    for (int st = 512; st > 0; st >>= 1) {
        if (t < st) sr[t] += sr[t + st];
        __syncthreads();
    }
    if (t == 0) {
        float m = sr[0] * inv_count;
        out[out_size - 2] = m;
        out[out_size - 1] = m;
    }
}

// ============================================================================
extern "C" void kernel_launch(void* const* d_in, const int* in_sizes, int n_in,
                              void* d_out, int out_size) {
    const float* x  = (const float*)d_in[0];
    const float* W  = (const float*)d_in[1];
    const float* b  = (const float*)d_in[2];
    const float* cb = (const float*)d_in[3];

    int M      = in_sizes[0] / D;   // 32768
    int Kcodes = in_sizes[3] / D;   // 8192
    int NT     = Kcodes / 128;      // 64
    float* out = (float*)d_out;

    cudaFuncSetAttribute(dist_mma_kernel,
                         cudaFuncAttributeMaxDynamicSharedMemorySize, DIST_SMEM);
    cudaFuncSetAttribute(proj_kernel,
                         cudaFuncAttributeMaxDynamicSharedMemorySize, PROJ_SMEM);

    // 1. fused codebook norms + bf16 hi split
    cnsplit_kernel<<<Kcodes / 8, 256>>>(cb);

    // 2. projection (exact fp32 z into out, plus bf16 hi of z), pipelined
    dim3 pg(M / BM, D / BN);
    proj_kernel<<<pg, NTHREADS, PROJ_SMEM>>>(x, W, b, out);

    // 3. HMMA distance GEMM (1-term, BK=64, 3-stage ring, 2 CTA/SM)
    dist_mma_kernel<<<dim3(M / 128, NT), 256, DIST_SMEM>>>(Kcodes);

    // 4. fused top-4 select + exact rescore + gather + loss partials
    rescore_gather_kernel<<<M / 8, 256>>>(out, cb, NT);

    // 5. finalize
    finalize_kernel<<<1, 1024>>>(out, out_size, 1.0f / (float)(M * D));
}

// round 15
// speedup vs baseline: 1.0987x; 1.0610x over previous
#include <cuda_runtime.h>
#include <cuda_bf16.h>
#include <math_constants.h>
#include <cstdint>

// ============================================================================
// Problem constants
// ============================================================================
#define D        256
#define MROWS    32768
#define KCODES   8192
#define NTILE    64            // KCODES / 128
#define BM       128
#define BN       128
#define BK       16
#define TM       8
#define TN       8
#define NTHREADS 256

// dist kernel smem geometry (CTA 64 rows x 128 codes, BK=64, 2-stage ring)
#define SB       72                    // bf16 row stride (144 B, ldsm conflict-free)
#define ATILEB   (64 * SB * 2)         // 9216 B  : 64x64 zh tile
#define BTILEB   (128 * SB * 2)        // 18432 B : 128x64 eh tile
#define STAGEB   (ATILEB + BTILEB)     // 27648 B per stage
#define DIST_SMEM (2 * STAGEB)         // 55296 B -> 4 CTAs/SM (216KB <= 228KB)

// proj kernel smem: 2 stages x 2 tiles x 16 x 132 floats
#define PROJ_SMEM (2 * 2 * BK * (BM + 4) * 4)   // 67584 B

// ============================================================================
// Device scratch (no cudaMalloc allowed)
// ============================================================================
__device__ float          g_cn[KCODES];
__device__ float          g_part[4096];
__device__ __nv_bfloat16  g_cbh[KCODES * D];
__device__ __nv_bfloat16  g_zh[MROWS * D];
__device__ float2         g_cv[(size_t)MROWS * NTILE];
__device__ int2           g_ci[(size_t)MROWS * NTILE];

// ============================================================================
// Helpers
// ============================================================================
__device__ __forceinline__ uint32_t smem_to_u32(const void* p) {
    uint32_t a;
    asm("{ .reg .u64 t; cvta.to.shared.u64 t, %1; cvt.u32.u64 %0, t; }"
        : "=r"(a) : "l"(p));
    return a;
}
__device__ __forceinline__ void cp16(uint32_t dst, const void* src) {
    asm volatile("cp.async.cg.shared.global [%0], [%1], 16;"
        :: "r"(dst), "l"(__cvta_generic_to_global(src)) : "memory");
}
__device__ __forceinline__ void ldsm_x4(uint32_t& r0, uint32_t& r1,
                                        uint32_t& r2, uint32_t& r3, uint32_t addr) {
    asm volatile("ldmatrix.sync.aligned.m8n8.x4.shared.b16 {%0,%1,%2,%3}, [%4];"
        : "=r"(r0), "=r"(r1), "=r"(r2), "=r"(r3) : "r"(addr));
}
__device__ __forceinline__ void mma16816(float* c, uint32_t a0, uint32_t a1,
                                         uint32_t a2, uint32_t a3,
                                         uint32_t b0, uint32_t b1) {
    asm volatile("mma.sync.aligned.m16n8k16.row.col.f32.bf16.bf16.f32 "
        "{%0,%1,%2,%3}, {%4,%5,%6,%7}, {%8,%9}, {%0,%1,%2,%3};"
        : "+f"(c[0]), "+f"(c[1]), "+f"(c[2]), "+f"(c[3])
        : "r"(a0), "r"(a1), "r"(a2), "r"(a3), "r"(b0), "r"(b1));
}
__device__ __forceinline__ void top2_merge(float& v0, int& i0, float& v1, int& i1,
                                           float w0, int j0, float w1, int j1) {
    if (w0 < v0) {
        if (v0 < w1) { v1 = v0; i1 = i0; } else { v1 = w1; i1 = j1; }
        v0 = w0; i0 = j0;
    } else if (w0 < v1) { v1 = w0; i1 = j0; }
}

// ============================================================================
// Kernel 1 (fused): blockIdx.y < 2  -> projection tile (exact fp32, pipelined,
//                   NUMERICS FROZEN) + bf16 hi split of z
//                   blockIdx.y == 2 -> codebook norms + bf16 hi split (32 rows
//                   per block, overlapped with projection)
// ============================================================================
__global__ __launch_bounds__(NTHREADS, 2)
void proj_cnsplit_kernel(const float* __restrict__ x, const float* __restrict__ W,
                         const float* __restrict__ b, const float* __restrict__ cb,
                         float* __restrict__ z) {
    if (blockIdx.y == 2) {
        // ---- codebook norms + hi-split: 32 rows per block, 4 per warp ----
        int lane = threadIdx.x & 31;
        int w = threadIdx.x >> 5;
#pragma unroll
        for (int rr = 0; rr < 4; ++rr) {
            int row = blockIdx.x * 32 + w * 4 + rr;
            const float4* src = reinterpret_cast<const float4*>(cb + (size_t)row * D);
            __nv_bfloat162* dh = reinterpret_cast<__nv_bfloat162*>(g_cbh + (size_t)row * D);
            float s = 0.f;
#pragma unroll
            for (int p = 0; p < 2; ++p) {
                int qq = lane + p * 32;
                float4 v = src[qq];
                s += v.x * v.x + v.y * v.y + v.z * v.z + v.w * v.w;
                dh[qq * 2 + 0] = __nv_bfloat162(__float2bfloat16(v.x), __float2bfloat16(v.y));
                dh[qq * 2 + 1] = __nv_bfloat162(__float2bfloat16(v.z), __float2bfloat16(v.w));
            }
#pragma unroll
            for (int o = 16; o > 0; o >>= 1) s += __shfl_xor_sync(0xffffffffu, s, o);
            if (lane == 0) g_cn[row] = s;
        }
        return;
    }

    // ---- projection tile ----
    extern __shared__ __align__(16) float psm[];
    const int TS = BK * (BM + 4);          // 2112 floats per tile

    int tid = threadIdx.x;
    int tx = tid & 15, ty = tid >> 4;
    int rowBase = blockIdx.x * BM;
    int colBase = blockIdx.y * BN;

    int r0i = (tid + 0) >> 2, c40 = (tid + 0) & 3;
    int r1i = (tid + 256) >> 2, c41 = (tid + 256) & 3;

    auto gload = [&](float4& vx0, float4& vx1, float4& vw0, float4& vw1, int kt) {
        vx0 = *reinterpret_cast<const float4*>(x + (size_t)(rowBase + r0i) * D + kt * BK + c40 * 4);
        vx1 = *reinterpret_cast<const float4*>(x + (size_t)(rowBase + r1i) * D + kt * BK + c41 * 4);
        vw0 = *reinterpret_cast<const float4*>(W + (size_t)(colBase + r0i) * D + kt * BK + c40 * 4);
        vw1 = *reinterpret_cast<const float4*>(W + (size_t)(colBase + r1i) * D + kt * BK + c41 * 4);
    };
    auto sts = [&](int s, const float4& vx0, const float4& vx1,
                   const float4& vw0, const float4& vw1) {
        float* Xs = psm + s * 2 * TS;
        float* Ws = Xs + TS;
        Xs[(c40 * 4 + 0) * 132 + r0i] = vx0.x;
        Xs[(c40 * 4 + 1) * 132 + r0i] = vx0.y;
        Xs[(c40 * 4 + 2) * 132 + r0i] = vx0.z;
        Xs[(c40 * 4 + 3) * 132 + r0i] = vx0.w;
        Xs[(c41 * 4 + 0) * 132 + r1i] = vx1.x;
        Xs[(c41 * 4 + 1) * 132 + r1i] = vx1.y;
        Xs[(c41 * 4 + 2) * 132 + r1i] = vx1.z;
        Xs[(c41 * 4 + 3) * 132 + r1i] = vx1.w;
        Ws[(c40 * 4 + 0) * 132 + r0i] = vw0.x;
        Ws[(c40 * 4 + 1) * 132 + r0i] = vw0.y;
        Ws[(c40 * 4 + 2) * 132 + r0i] = vw0.z;
        Ws[(c40 * 4 + 3) * 132 + r0i] = vw0.w;
        Ws[(c41 * 4 + 0) * 132 + r1i] = vw1.x;
        Ws[(c41 * 4 + 1) * 132 + r1i] = vw1.y;
        Ws[(c41 * 4 + 2) * 132 + r1i] = vw1.z;
        Ws[(c41 * 4 + 3) * 132 + r1i] = vw1.w;
    };

    float acc[TM][TN];
#pragma unroll
    for (int i = 0; i < TM; ++i)
#pragma unroll
        for (int j = 0; j < TN; ++j) acc[i][j] = 0.f;

    float4 px0, px1, pw0, pw1;
    gload(px0, px1, pw0, pw1, 0);
    sts(0, px0, px1, pw0, pw1);
    __syncthreads();

    for (int kt = 0; kt < D / BK; ++kt) {
        int s = kt & 1;
        if (kt < D / BK - 1) gload(px0, px1, pw0, pw1, kt + 1);
        const float* Xs = psm + s * 2 * TS;
        const float* Ws = Xs + TS;
#pragma unroll
        for (int kk = 0; kk < BK; ++kk) {
            float a[TM], bb[TN];
#pragma unroll
            for (int i = 0; i < TM; ++i) a[i] = Xs[kk * 132 + ty * TM + i];
#pragma unroll
            for (int j = 0; j < TN; ++j) bb[j] = Ws[kk * 132 + tx * TN + j];
#pragma unroll
            for (int i = 0; i < TM; ++i)
#pragma unroll
                for (int j = 0; j < TN; ++j)
                    acc[i][j] = fmaf(a[i], bb[j], acc[i][j]);
        }
        if (kt < D / BK - 1) sts(s ^ 1, px0, px1, pw0, pw1);
        __syncthreads();
    }

    int col0 = colBase + tx * TN;
#pragma unroll
    for (int i = 0; i < TM; ++i) {
        int row = rowBase + ty * TM + i;
        float* zrow = z + (size_t)row * D + col0;
        __nv_bfloat162* hrow = reinterpret_cast<__nv_bfloat162*>(g_zh + (size_t)row * D) + (col0 >> 1);
#pragma unroll
        for (int j4 = 0; j4 < TN / 4; ++j4) {
            float4 v;
            v.x = acc[i][j4 * 4 + 0] + b[col0 + j4 * 4 + 0];
            v.y = acc[i][j4 * 4 + 1] + b[col0 + j4 * 4 + 1];
            v.z = acc[i][j4 * 4 + 2] + b[col0 + j4 * 4 + 2];
            v.w = acc[i][j4 * 4 + 3] + b[col0 + j4 * 4 + 3];
            *reinterpret_cast<float4*>(zrow + j4 * 4) = v;
            hrow[j4 * 2 + 0] = __nv_bfloat162(__float2bfloat16(v.x), __float2bfloat16(v.y));
            hrow[j4 * 2 + 1] = __nv_bfloat162(__float2bfloat16(v.z), __float2bfloat16(v.w));
        }
    }
}

// ============================================================================
// Kernel 2: distance GEMM on HMMA, 1-term (dot = zh.eh).
// CTA 64 rows x 128 codes, 4 warps 2(m) x 2(n), warp tile 32x64.
// 4 CTAs/SM (same 16 warps/SM as R12 but finer sync domains: each barrier
// aligns only 4 warps; 4 independent CTAs hide each other's drain bubbles).
// BK=64, 2-stage ring, prefetch during compute.
// ============================================================================
__global__ __launch_bounds__(128, 4)
void dist_mma_kernel(int Kcodes) {
    extern __shared__ __align__(16) char smem[];
    const uint32_t smBase = smem_to_u32(smem);

    const int tid = threadIdx.x, lane = tid & 31, wid = tid >> 5;
    const int wm = wid >> 1, wn = wid & 1;        // 2 x 2 warp grid
    const int rowBase = blockIdx.x * 64;
    const int codeBase = blockIdx.y * 128;

    const int q = lane >> 3, i8 = lane & 7;
    const uint32_t aOff = (uint32_t)(((wm * 32 + (q & 1) * 8 + i8) * SB + (q >> 1) * 8) * 2);
    const uint32_t bOff = (uint32_t)(((wn * 64 + (q >> 1) * 8 + i8) * SB + (q & 1) * 8) * 2);

    float acc[2][8][4];
#pragma unroll
    for (int mt = 0; mt < 2; ++mt)
#pragma unroll
        for (int nt = 0; nt < 8; ++nt)
#pragma unroll
            for (int e = 0; e < 4; ++e) acc[mt][nt][e] = 0.f;

    // stage k-chunk kt (64 k): zh 512 chunks + eh 1024 chunks, 12/thread
    auto stage = [&](int buf, int kt) {
        uint32_t base = smBase + (uint32_t)buf * STAGEB;
        int kc = kt * 64;
#pragma unroll
        for (int i = 0; i < 12; ++i) {
            int c = tid + i * 128;              // 0..1535
            if (c < 512) {
                int hf = c & 7, r = c >> 3;     // zh row 0..63
                cp16(base + (uint32_t)(r * (SB * 2) + hf * 16),
                     g_zh + (size_t)(rowBase + r) * D + kc + hf * 8);
            } else {
                int cc = c - 512;
                int hf = cc & 7, r = cc >> 3;   // eh row 0..127
                cp16(base + ATILEB + (uint32_t)(r * (SB * 2) + hf * 16),
                     g_cbh + (size_t)(codeBase + r) * D + kc + hf * 8);
            }
        }
        asm volatile("cp.async.commit_group;" ::: "memory");
    };

    auto load_frags = [&](uint32_t* ah, uint32_t (*bfr)[2], uint32_t tb, int kh) {
#pragma unroll
        for (int mt = 0; mt < 2; ++mt)
            ldsm_x4(ah[mt * 4 + 0], ah[mt * 4 + 1], ah[mt * 4 + 2], ah[mt * 4 + 3],
                    tb + aOff + (uint32_t)(mt * 16 * SB * 2 + kh * 32));
#pragma unroll
        for (int nt2 = 0; nt2 < 4; ++nt2) {
            uint32_t r0, r1, r2, r3;
            ldsm_x4(r0, r1, r2, r3,
                    tb + ATILEB + bOff + (uint32_t)(nt2 * 16 * SB * 2 + kh * 32));
            bfr[nt2 * 2 + 0][0] = r0; bfr[nt2 * 2 + 0][1] = r1;
            bfr[nt2 * 2 + 1][0] = r2; bfr[nt2 * 2 + 1][1] = r3;
        }
    };

    auto mma_all = [&](uint32_t* ah, uint32_t (*bfr)[2]) {
#pragma unroll
        for (int mt = 0; mt < 2; ++mt)
#pragma unroll
            for (int nt = 0; nt < 8; ++nt)
                mma16816(acc[mt][nt], ah[mt * 4 + 0], ah[mt * 4 + 1],
                         ah[mt * 4 + 2], ah[mt * 4 + 3],
                         bfr[nt][0], bfr[nt][1]);
    };

    stage(0, 0);

    uint32_t ahF[8];
    uint32_t bfF[8][2];

#pragma unroll
    for (int kt = 0; kt < 4; ++kt) {
        asm volatile("cp.async.wait_group 0;" ::: "memory");
        __syncthreads();                 // publish buf kt; retire reads of the other buf
        if (kt < 3) stage((kt + 1) & 1, kt + 1);

        uint32_t tb = smBase + (uint32_t)(kt & 1) * STAGEB;
#pragma unroll
        for (int kh = 0; kh < 4; ++kh) {
            load_frags(ahF, bfF, tb, kh);
            mma_all(ahF, bfF);
        }
    }

    // ---- epilogue: d = cn - 2*dot, per-row top-2 over this CTA's 128 codes ----
    __syncthreads();                      // mainloop smem dead; alias as red[]
    float4 (*red)[2] = reinterpret_cast<float4(*)[2]>(smem);

    const int g = lane >> 2;
    const int cb0 = codeBase + wn * 64 + (lane & 3) * 2;
    float cn8[8][2];
#pragma unroll
    for (int nt = 0; nt < 8; ++nt) {
        cn8[nt][0] = __ldg(&g_cn[cb0 + nt * 8 + 0]);
        cn8[nt][1] = __ldg(&g_cn[cb0 + nt * 8 + 1]);
    }
#pragma unroll
    for (int mt = 0; mt < 2; ++mt)
#pragma unroll
        for (int h = 0; h < 2; ++h) {
            float v0 = CUDART_INF_F, v1 = CUDART_INF_F;
            int i0 = 0, i1 = 0;
#pragma unroll
            for (int nt = 0; nt < 8; ++nt)
#pragma unroll
                for (int e = 0; e < 2; ++e) {
                    float dd = fmaf(-2.f, acc[mt][nt][h * 2 + e], cn8[nt][e]);
                    int code = cb0 + nt * 8 + e;
                    if (dd < v0) { v1 = v0; i1 = i0; v0 = dd; i0 = code; }
                    else if (dd < v1) { v1 = dd; i1 = code; }
                }
#pragma unroll
            for (int off = 1; off <= 2; off <<= 1) {
                float w0 = __shfl_xor_sync(0xffffffffu, v0, off);
                float w1 = __shfl_xor_sync(0xffffffffu, v1, off);
                int j0 = __shfl_xor_sync(0xffffffffu, i0, off);
                int j1 = __shfl_xor_sync(0xffffffffu, i1, off);
                top2_merge(v0, i0, v1, i1, w0, j0, w1, j1);
            }
            if ((lane & 3) == 0)
                red[wm * 32 + mt * 16 + h * 8 + g][wn] =
                    make_float4(v0, __int_as_float(i0), v1, __int_as_float(i1));
        }
    __syncthreads();

    if (tid < 64) {
        float4 p0 = red[tid][0];
        float4 p1 = red[tid][1];
        float v0 = p0.x, v1 = p0.z;
        int i0 = __float_as_int(p0.y), i1 = __float_as_int(p0.w);
        top2_merge(v0, i0, v1, i1, p1.x, __float_as_int(p1.y), p1.z, __float_as_int(p1.w));
        size_t slot = (size_t)(rowBase + tid) * gridDim.y + blockIdx.y;
        g_cv[slot] = make_float2(v0, v1);
        g_ci[slot] = make_int2(i0, i1);
    }
}

// ============================================================================
// Kernel 3 (fused): per-row approx top-4 + exact fp32 rescore + gather q into
// out + elementwise loss partial. One warp per row; 8 rows per block.
// ============================================================================
__global__ __launch_bounds__(256)
void rescore_gather_kernel(float* __restrict__ out,
                           const float* __restrict__ cb, int NT) {
    __shared__ float wloss[8];
    int warp = threadIdx.x >> 5;
    int row = blockIdx.x * 8 + warp;
    int lane = threadIdx.x & 31;

    float vv[4] = { CUDART_INF_F, CUDART_INF_F, CUDART_INF_F, CUDART_INF_F };
    int ii[4] = { 0x7fffffff, 0x7fffffff, 0x7fffffff, 0x7fffffff };
    if (lane < NT) {
        float2 cv = g_cv[(size_t)row * NT + lane];
        int2 ci = g_ci[(size_t)row * NT + lane];
        vv[0] = cv.x; ii[0] = ci.x;
        vv[1] = cv.y; ii[1] = ci.y;
    }
    if (lane + 32 < NT) {
        float2 cv = g_cv[(size_t)row * NT + lane + 32];
        int2 ci = g_ci[(size_t)row * NT + lane + 32];
        vv[2] = cv.x; ii[2] = ci.x;
        vv[3] = cv.y; ii[3] = ci.y;
    }

    int jj[4];
#pragma unroll
    for (int r = 0; r < 4; ++r) {
        float bv = CUDART_INF_F; int bi = 0x7fffffff;
#pragma unroll
        for (int k = 0; k < 4; ++k)
            if (vv[k] < bv || (vv[k] == bv && ii[k] < bi)) { bv = vv[k]; bi = ii[k]; }
#pragma unroll
        for (int off = 16; off > 0; off >>= 1) {
            float wv = __shfl_xor_sync(0xffffffffu, bv, off);
            int wi = __shfl_xor_sync(0xffffffffu, bi, off);
            if (wv < bv || (wv == bv && wi < bi)) { bv = wv; bi = wi; }
        }
        jj[r] = (bi == 0x7fffffff) ? 0 : bi;
#pragma unroll
        for (int k = 0; k < 4; ++k)
            if (ii[k] == bi) { vv[k] = CUDART_INF_F; ii[k] = 0x7fffffff; }
    }

    float4* zr = reinterpret_cast<float4*>(out + (size_t)row * D);
    float4 z0 = zr[lane], z1 = zr[lane + 32];
    float s4[4];
#pragma unroll
    for (int j = 0; j < 4; ++j) {
        const float4* ej = reinterpret_cast<const float4*>(cb + (size_t)jj[j] * D);
        float4 a = ej[lane];
        float4 c = ej[lane + 32];
        float s = 0.f;
        s = fmaf(z0.x, a.x, s); s = fmaf(z0.y, a.y, s);
        s = fmaf(z0.z, a.z, s); s = fmaf(z0.w, a.w, s);
        s = fmaf(z1.x, c.x, s); s = fmaf(z1.y, c.y, s);
        s = fmaf(z1.z, c.z, s); s = fmaf(z1.w, c.w, s);
        s4[j] = s;
    }
#pragma unroll
    for (int off = 16; off > 0; off >>= 1) {
#pragma unroll
        for (int j = 0; j < 4; ++j)
            s4[j] += __shfl_xor_sync(0xffffffffu, s4[j], off);
    }
    float best = CUDART_INF_F; int bi = 0x7fffffff;
#pragma unroll
    for (int j = 0; j < 4; ++j) {
        float dj = g_cn[jj[j]] - 2.f * s4[j];
        if (dj < best || (dj == best && jj[j] < bi)) { best = dj; bi = jj[j]; }
    }

    const float4* ew = reinterpret_cast<const float4*>(cb + (size_t)bi * D);
    float ls = 0.f;
    {
        float4 qv = ew[lane];
        zr[lane] = qv;
        float dx = z0.x - qv.x, dy = z0.y - qv.y;
        float dz = z0.z - qv.z, dw = z0.w - qv.w;
        ls += dx * dx + dy * dy + dz * dz + dw * dw;
        qv = ew[lane + 32];
        zr[lane + 32] = qv;
        dx = z1.x - qv.x; dy = z1.y - qv.y;
        dz = z1.z - qv.z; dw = z1.w - qv.w;
        ls += dx * dx + dy * dy + dz * dz + dw * dw;
    }
#pragma unroll
    for (int off = 16; off > 0; off >>= 1)
        ls += __shfl_xor_sync(0xffffffffu, ls, off);
    if (lane == 0) wloss[warp] = ls;
    __syncthreads();
    if (threadIdx.x == 0) {
        float t = 0.f;
#pragma unroll
        for (int w = 0; w < 8; ++w) t += wloss[w];
        g_part[blockIdx.x] = t;
    }
}

// ============================================================================
// Kernel 4: finalize losses (4096 partials, deterministic tree)
// ============================================================================
__global__ __launch_bounds__(1024)
void finalize_kernel(float* __restrict__ out, int out_size, float inv_count) {
    __shared__ float sr[1024];
    int t = threadIdx.x;
    float s = 0.f;
#pragma unroll
    for (int p = 0; p < 4; ++p) s += g_part[t + p * 1024];
    sr[t] = s;
    __syncthreads();
    for (int st = 512; st > 0; st >>= 1) {
        if (t < st) sr[t] += sr[t + st];
        __syncthreads();
    }
    if (t == 0) {
        float m = sr[0] * inv_count;
        out[out_size - 2] = m;
        out[out_size - 1] = m;
    }
}

// ============================================================================
extern "C" void kernel_launch(void* const* d_in, const int* in_sizes, int n_in,
                              void* d_out, int out_size) {
    const float* x  = (const float*)d_in[0];
    const float* W  = (const float*)d_in[1];
    const float* b  = (const float*)d_in[2];
    const float* cb = (const float*)d_in[3];

    int M      = in_sizes[0] / D;   // 32768
    int Kcodes = in_sizes[3] / D;   // 8192
    int NT     = Kcodes / 128;      // 64
    float* out = (float*)d_out;

    cudaFuncSetAttribute(dist_mma_kernel,
                         cudaFuncAttributeMaxDynamicSharedMemorySize, DIST_SMEM);
    cudaFuncSetAttribute(proj_cnsplit_kernel,
                         cudaFuncAttributeMaxDynamicSharedMemorySize, PROJ_SMEM);

    // 1. fused projection + codebook norms/split (overlapped in one launch)
    //    y < 2: proj tiles; y == 2: cnsplit (Kcodes/32 = 256 <= M/BM grid.x)
    dim3 pg(M / BM, 3);
    proj_cnsplit_kernel<<<pg, NTHREADS, PROJ_SMEM>>>(x, W, b, cb, out);

    // 2. HMMA distance GEMM (1-term, CTA 64x128, 4 CTAs/SM)
    dist_mma_kernel<<<dim3(M / 64, NT), 128, DIST_SMEM>>>(Kcodes);

    // 3. fused top-4 select + exact rescore + gather + loss partials
    rescore_gather_kernel<<<M / 8, 256>>>(out, cb, NT);

    // 4. finalize
    finalize_kernel<<<1, 1024>>>(out, out_size, 1.0f / (float)(M * D));
}

// round 16
// speedup vs baseline: 1.1104x; 1.0107x over previous
#include <cuda_runtime.h>
#include <cuda_bf16.h>
#include <math_constants.h>
#include <cstdint>

// ============================================================================
// Problem constants
// ============================================================================
#define D        256
#define MROWS    32768
#define KCODES   8192
#define NTILE    64            // KCODES / 128
#define BM       128
#define BN       128
#define BK       16
#define TM       8
#define TN       8
#define NTHREADS 256

// dist kernel smem geometry (CTA 64 rows x 128 codes, BK=64, 2-stage ring)
#define SB       72                    // bf16 row stride (144 B, ldsm conflict-free)
#define ATILEB   (64 * SB * 2)         // 9216 B  : 64x64 zh tile
#define BTILEB   (128 * SB * 2)        // 18432 B : 128x64 eh tile
#define STAGEB   (ATILEB + BTILEB)     // 27648 B per stage
#define DIST_SMEM (2 * STAGEB)         // 55296 B -> 4 CTAs/SM (216KB <= 228KB)

// proj kernel smem: 2 stages x 2 tiles x 16 x 132 floats
#define PROJ_SMEM (2 * 2 * BK * (BM + 4) * 4)   // 67584 B

// ============================================================================
// Device scratch (no cudaMalloc allowed)
// ============================================================================
__device__ float          g_cn[KCODES];
__device__ float          g_part[4096];
__device__ __nv_bfloat16  g_cbh[KCODES * D];
__device__ __nv_bfloat16  g_zh[MROWS * D];
__device__ float2         g_cv[(size_t)MROWS * NTILE];
__device__ int2           g_ci[(size_t)MROWS * NTILE];

// ============================================================================
// Helpers
// ============================================================================
__device__ __forceinline__ uint32_t smem_to_u32(const void* p) {
    uint32_t a;
    asm("{ .reg .u64 t; cvta.to.shared.u64 t, %1; cvt.u32.u64 %0, t; }"
        : "=r"(a) : "l"(p));
    return a;
}
__device__ __forceinline__ void cp16(uint32_t dst, const void* src) {
    asm volatile("cp.async.cg.shared.global [%0], [%1], 16;"
        :: "r"(dst), "l"(__cvta_generic_to_global(src)) : "memory");
}
__device__ __forceinline__ void ldsm_x4(uint32_t& r0, uint32_t& r1,
                                        uint32_t& r2, uint32_t& r3, uint32_t addr) {
    asm volatile("ldmatrix.sync.aligned.m8n8.x4.shared.b16 {%0,%1,%2,%3}, [%4];"
        : "=r"(r0), "=r"(r1), "=r"(r2), "=r"(r3) : "r"(addr));
}
__device__ __forceinline__ void mma16816(float* c, uint32_t a0, uint32_t a1,
                                         uint32_t a2, uint32_t a3,
                                         uint32_t b0, uint32_t b1) {
    asm volatile("mma.sync.aligned.m16n8k16.row.col.f32.bf16.bf16.f32 "
        "{%0,%1,%2,%3}, {%4,%5,%6,%7}, {%8,%9}, {%0,%1,%2,%3};"
        : "+f"(c[0]), "+f"(c[1]), "+f"(c[2]), "+f"(c[3])
        : "r"(a0), "r"(a1), "r"(a2), "r"(a3), "r"(b0), "r"(b1));
}
__device__ __forceinline__ void top2_merge(float& v0, int& i0, float& v1, int& i1,
                                           float w0, int j0, float w1, int j1) {
    if (w0 < v0) {
        if (v0 < w1) { v1 = v0; i1 = i0; } else { v1 = w1; i1 = j1; }
        v0 = w0; i0 = j0;
    } else if (w0 < v1) { v1 = w0; i1 = j0; }
}

// ============================================================================
// Kernel 1 (fused): blockIdx.y < 2  -> projection tile (exact fp32, pipelined,
//                   NUMERICS FROZEN) + bf16 hi split of z
//                   blockIdx.y == 2 -> codebook norms + bf16 hi split
// ============================================================================
__global__ __launch_bounds__(NTHREADS, 2)
void proj_cnsplit_kernel(const float* __restrict__ x, const float* __restrict__ W,
                         const float* __restrict__ b, const float* __restrict__ cb,
                         float* __restrict__ z) {
    if (blockIdx.y == 2) {
        int lane = threadIdx.x & 31;
        int w = threadIdx.x >> 5;
#pragma unroll
        for (int rr = 0; rr < 4; ++rr) {
            int row = blockIdx.x * 32 + w * 4 + rr;
            const float4* src = reinterpret_cast<const float4*>(cb + (size_t)row * D);
            __nv_bfloat162* dh = reinterpret_cast<__nv_bfloat162*>(g_cbh + (size_t)row * D);
            float s = 0.f;
#pragma unroll
            for (int p = 0; p < 2; ++p) {
                int qq = lane + p * 32;
                float4 v = src[qq];
                s += v.x * v.x + v.y * v.y + v.z * v.z + v.w * v.w;
                dh[qq * 2 + 0] = __nv_bfloat162(__float2bfloat16(v.x), __float2bfloat16(v.y));
                dh[qq * 2 + 1] = __nv_bfloat162(__float2bfloat16(v.z), __float2bfloat16(v.w));
            }
#pragma unroll
            for (int o = 16; o > 0; o >>= 1) s += __shfl_xor_sync(0xffffffffu, s, o);
            if (lane == 0) g_cn[row] = s;
        }
        return;
    }

    extern __shared__ __align__(16) float psm[];
    const int TS = BK * (BM + 4);          // 2112 floats per tile

    int tid = threadIdx.x;
    int tx = tid & 15, ty = tid >> 4;
    int rowBase = blockIdx.x * BM;
    int colBase = blockIdx.y * BN;

    int r0i = (tid + 0) >> 2, c40 = (tid + 0) & 3;
    int r1i = (tid + 256) >> 2, c41 = (tid + 256) & 3;

    auto gload = [&](float4& vx0, float4& vx1, float4& vw0, float4& vw1, int kt) {
        vx0 = *reinterpret_cast<const float4*>(x + (size_t)(rowBase + r0i) * D + kt * BK + c40 * 4);
        vx1 = *reinterpret_cast<const float4*>(x + (size_t)(rowBase + r1i) * D + kt * BK + c41 * 4);
        vw0 = *reinterpret_cast<const float4*>(W + (size_t)(colBase + r0i) * D + kt * BK + c40 * 4);
        vw1 = *reinterpret_cast<const float4*>(W + (size_t)(colBase + r1i) * D + kt * BK + c41 * 4);
    };
    auto sts = [&](int s, const float4& vx0, const float4& vx1,
                   const float4& vw0, const float4& vw1) {
        float* Xs = psm + s * 2 * TS;
        float* Ws = Xs + TS;
        Xs[(c40 * 4 + 0) * 132 + r0i] = vx0.x;
        Xs[(c40 * 4 + 1) * 132 + r0i] = vx0.y;
        Xs[(c40 * 4 + 2) * 132 + r0i] = vx0.z;
        Xs[(c40 * 4 + 3) * 132 + r0i] = vx0.w;
        Xs[(c41 * 4 + 0) * 132 + r1i] = vx1.x;
        Xs[(c41 * 4 + 1) * 132 + r1i] = vx1.y;
        Xs[(c41 * 4 + 2) * 132 + r1i] = vx1.z;
        Xs[(c41 * 4 + 3) * 132 + r1i] = vx1.w;
        Ws[(c40 * 4 + 0) * 132 + r0i] = vw0.x;
        Ws[(c40 * 4 + 1) * 132 + r0i] = vw0.y;
        Ws[(c40 * 4 + 2) * 132 + r0i] = vw0.z;
        Ws[(c40 * 4 + 3) * 132 + r0i] = vw0.w;
        Ws[(c41 * 4 + 0) * 132 + r1i] = vw1.x;
        Ws[(c41 * 4 + 1) * 132 + r1i] = vw1.y;
        Ws[(c41 * 4 + 2) * 132 + r1i] = vw1.z;
        Ws[(c41 * 4 + 3) * 132 + r1i] = vw1.w;
    };

    float acc[TM][TN];
#pragma unroll
    for (int i = 0; i < TM; ++i)
#pragma unroll
        for (int j = 0; j < TN; ++j) acc[i][j] = 0.f;

    float4 px0, px1, pw0, pw1;
    gload(px0, px1, pw0, pw1, 0);
    sts(0, px0, px1, pw0, pw1);
    __syncthreads();

    for (int kt = 0; kt < D / BK; ++kt) {
        int s = kt & 1;
        if (kt < D / BK - 1) gload(px0, px1, pw0, pw1, kt + 1);
        const float* Xs = psm + s * 2 * TS;
        const float* Ws = Xs + TS;
#pragma unroll
        for (int kk = 0; kk < BK; ++kk) {
            float a[TM], bb[TN];
#pragma unroll
            for (int i = 0; i < TM; ++i) a[i] = Xs[kk * 132 + ty * TM + i];
#pragma unroll
            for (int j = 0; j < TN; ++j) bb[j] = Ws[kk * 132 + tx * TN + j];
#pragma unroll
            for (int i = 0; i < TM; ++i)
#pragma unroll
                for (int j = 0; j < TN; ++j)
                    acc[i][j] = fmaf(a[i], bb[j], acc[i][j]);
        }
        if (kt < D / BK - 1) sts(s ^ 1, px0, px1, pw0, pw1);
        __syncthreads();
    }

    int col0 = colBase + tx * TN;
#pragma unroll
    for (int i = 0; i < TM; ++i) {
        int row = rowBase + ty * TM + i;
        float* zrow = z + (size_t)row * D + col0;
        __nv_bfloat162* hrow = reinterpret_cast<__nv_bfloat162*>(g_zh + (size_t)row * D) + (col0 >> 1);
#pragma unroll
        for (int j4 = 0; j4 < TN / 4; ++j4) {
            float4 v;
            v.x = acc[i][j4 * 4 + 0] + b[col0 + j4 * 4 + 0];
            v.y = acc[i][j4 * 4 + 1] + b[col0 + j4 * 4 + 1];
            v.z = acc[i][j4 * 4 + 2] + b[col0 + j4 * 4 + 2];
            v.w = acc[i][j4 * 4 + 3] + b[col0 + j4 * 4 + 3];
            *reinterpret_cast<float4*>(zrow + j4 * 4) = v;
            hrow[j4 * 2 + 0] = __nv_bfloat162(__float2bfloat16(v.x), __float2bfloat16(v.y));
            hrow[j4 * 2 + 1] = __nv_bfloat162(__float2bfloat16(v.z), __float2bfloat16(v.w));
        }
    }
}

// ============================================================================
// Kernel 2: distance GEMM on HMMA, 1-term (dot = zh.eh).
// CTA 64 rows x 128 codes, 4 warps 2(m) x 2(n), warp tile 32x64, 4 CTAs/SM.
// BK=64, 2-stage ring + intra-kt register fragment double buffering:
// ldsm of k16 half kh+1 issues during MMAs of half kh (no barrier between).
// ============================================================================
__global__ __launch_bounds__(128, 4)
void dist_mma_kernel(int Kcodes) {
    extern __shared__ __align__(16) char smem[];
    const uint32_t smBase = smem_to_u32(smem);

    const int tid = threadIdx.x, lane = tid & 31, wid = tid >> 5;
    const int wm = wid >> 1, wn = wid & 1;        // 2 x 2 warp grid
    const int rowBase = blockIdx.x * 64;
    const int codeBase = blockIdx.y * 128;

    const int q = lane >> 3, i8 = lane & 7;
    const uint32_t aOff = (uint32_t)(((wm * 32 + (q & 1) * 8 + i8) * SB + (q >> 1) * 8) * 2);
    const uint32_t bOff = (uint32_t)(((wn * 64 + (q >> 1) * 8 + i8) * SB + (q & 1) * 8) * 2);

    float acc[2][8][4];
#pragma unroll
    for (int mt = 0; mt < 2; ++mt)
#pragma unroll
        for (int nt = 0; nt < 8; ++nt)
#pragma unroll
            for (int e = 0; e < 4; ++e) acc[mt][nt][e] = 0.f;

    auto stage = [&](int buf, int kt) {
        uint32_t base = smBase + (uint32_t)buf * STAGEB;
        int kc = kt * 64;
#pragma unroll
        for (int i = 0; i < 12; ++i) {
            int c = tid + i * 128;              // 0..1535
            if (c < 512) {
                int hf = c & 7, r = c >> 3;     // zh row 0..63
                cp16(base + (uint32_t)(r * (SB * 2) + hf * 16),
                     g_zh + (size_t)(rowBase + r) * D + kc + hf * 8);
            } else {
                int cc = c - 512;
                int hf = cc & 7, r = cc >> 3;   // eh row 0..127
                cp16(base + ATILEB + (uint32_t)(r * (SB * 2) + hf * 16),
                     g_cbh + (size_t)(codeBase + r) * D + kc + hf * 8);
            }
        }
        asm volatile("cp.async.commit_group;" ::: "memory");
    };

    auto load_frags = [&](uint32_t* ah, uint32_t (*bfr)[2], uint32_t tb, int kh) {
#pragma unroll
        for (int mt = 0; mt < 2; ++mt)
            ldsm_x4(ah[mt * 4 + 0], ah[mt * 4 + 1], ah[mt * 4 + 2], ah[mt * 4 + 3],
                    tb + aOff + (uint32_t)(mt * 16 * SB * 2 + kh * 32));
#pragma unroll
        for (int nt2 = 0; nt2 < 4; ++nt2) {
            uint32_t r0, r1, r2, r3;
            ldsm_x4(r0, r1, r2, r3,
                    tb + ATILEB + bOff + (uint32_t)(nt2 * 16 * SB * 2 + kh * 32));
            bfr[nt2 * 2 + 0][0] = r0; bfr[nt2 * 2 + 0][1] = r1;
            bfr[nt2 * 2 + 1][0] = r2; bfr[nt2 * 2 + 1][1] = r3;
        }
    };

    auto mma_all = [&](uint32_t* ah, uint32_t (*bfr)[2]) {
#pragma unroll
        for (int mt = 0; mt < 2; ++mt)
#pragma unroll
            for (int nt = 0; nt < 8; ++nt)
                mma16816(acc[mt][nt], ah[mt * 4 + 0], ah[mt * 4 + 1],
                         ah[mt * 4 + 2], ah[mt * 4 + 3],
                         bfr[nt][0], bfr[nt][1]);
    };

    stage(0, 0);

    uint32_t ahF[2][8];
    uint32_t bfF[2][8][2];

#pragma unroll
    for (int kt = 0; kt < 4; ++kt) {
        asm volatile("cp.async.wait_group 0;" ::: "memory");
        __syncthreads();                 // publish buf kt; retire reads of the other buf
        if (kt < 3) stage((kt + 1) & 1, kt + 1);

        uint32_t tb = smBase + (uint32_t)(kt & 1) * STAGEB;

        // intra-kt pipelined: load kh+1 frags during kh MMAs
        load_frags(ahF[0], bfF[0], tb, 0);
        load_frags(ahF[1], bfF[1], tb, 1);  mma_all(ahF[0], bfF[0]);
        load_frags(ahF[0], bfF[0], tb, 2);  mma_all(ahF[1], bfF[1]);
        load_frags(ahF[1], bfF[1], tb, 3);  mma_all(ahF[0], bfF[0]);
        mma_all(ahF[1], bfF[1]);
    }

    // ---- epilogue: d = cn - 2*dot, per-row top-2 over this CTA's 128 codes ----
    __syncthreads();                      // mainloop smem dead; alias as red[]
    float4 (*red)[2] = reinterpret_cast<float4(*)[2]>(smem);

    const int g = lane >> 2;
    const int cb0 = codeBase + wn * 64 + (lane & 3) * 2;
    float cn8[8][2];
#pragma unroll
    for (int nt = 0; nt < 8; ++nt) {
        cn8[nt][0] = __ldg(&g_cn[cb0 + nt * 8 + 0]);
        cn8[nt][1] = __ldg(&g_cn[cb0 + nt * 8 + 1]);
    }
#pragma unroll
    for (int mt = 0; mt < 2; ++mt)
#pragma unroll
        for (int h = 0; h < 2; ++h) {
            float v0 = CUDART_INF_F, v1 = CUDART_INF_F;
            int i0 = 0, i1 = 0;
#pragma unroll
            for (int nt = 0; nt < 8; ++nt)
#pragma unroll
                for (int e = 0; e < 2; ++e) {
                    float dd = fmaf(-2.f, acc[mt][nt][h * 2 + e], cn8[nt][e]);
                    int code = cb0 + nt * 8 + e;
                    if (dd < v0) { v1 = v0; i1 = i0; v0 = dd; i0 = code; }
                    else if (dd < v1) { v1 = dd; i1 = code; }
                }
#pragma unroll
            for (int off = 1; off <= 2; off <<= 1) {
                float w0 = __shfl_xor_sync(0xffffffffu, v0, off);
                float w1 = __shfl_xor_sync(0xffffffffu, v1, off);
                int j0 = __shfl_xor_sync(0xffffffffu, i0, off);
                int j1 = __shfl_xor_sync(0xffffffffu, i1, off);
                top2_merge(v0, i0, v1, i1, w0, j0, w1, j1);
            }
            if ((lane & 3) == 0)
                red[wm * 32 + mt * 16 + h * 8 + g][wn] =
                    make_float4(v0, __int_as_float(i0), v1, __int_as_float(i1));
        }
    __syncthreads();

    if (tid < 64) {
        float4 p0 = red[tid][0];
        float4 p1 = red[tid][1];
        float v0 = p0.x, v1 = p0.z;
        int i0 = __float_as_int(p0.y), i1 = __float_as_int(p0.w);
        top2_merge(v0, i0, v1, i1, p1.x, __float_as_int(p1.y), p1.z, __float_as_int(p1.w));
        size_t slot = (size_t)(rowBase + tid) * gridDim.y + blockIdx.y;
        g_cv[slot] = make_float2(v0, v1);
        g_ci[slot] = make_int2(i0, i1);
    }
}

// ============================================================================
// Kernel 3 (fused): per-row approx top-4 + exact fp32 rescore + gather q into
// out + elementwise loss partial. One warp per row; 8 rows per block.
// ============================================================================
__global__ __launch_bounds__(256)
void rescore_gather_kernel(float* __restrict__ out,
                           const float* __restrict__ cb, int NT) {
    __shared__ float wloss[8];
    int warp = threadIdx.x >> 5;
    int row = blockIdx.x * 8 + warp;
    int lane = threadIdx.x & 31;

    float vv[4] = { CUDART_INF_F, CUDART_INF_F, CUDART_INF_F, CUDART_INF_F };
    int ii[4] = { 0x7fffffff, 0x7fffffff, 0x7fffffff, 0x7fffffff };
    if (lane < NT) {
        float2 cv = g_cv[(size_t)row * NT + lane];
        int2 ci = g_ci[(size_t)row * NT + lane];
        vv[0] = cv.x; ii[0] = ci.x;
        vv[1] = cv.y; ii[1] = ci.y;
    }
    if (lane + 32 < NT) {
        float2 cv = g_cv[(size_t)row * NT + lane + 32];
        int2 ci = g_ci[(size_t)row * NT + lane + 32];
        vv[2] = cv.x; ii[2] = ci.x;
        vv[3] = cv.y; ii[3] = ci.y;
    }

    int jj[4];
#pragma unroll
    for (int r = 0; r < 4; ++r) {
        float bv = CUDART_INF_F; int bi = 0x7fffffff;
#pragma unroll
        for (int k = 0; k < 4; ++k)
            if (vv[k] < bv || (vv[k] == bv && ii[k] < bi)) { bv = vv[k]; bi = ii[k]; }
#pragma unroll
        for (int off = 16; off > 0; off >>= 1) {
            float wv = __shfl_xor_sync(0xffffffffu, bv, off);
            int wi = __shfl_xor_sync(0xffffffffu, bi, off);
            if (wv < bv || (wv == bv && wi < bi)) { bv = wv; bi = wi; }
        }
        jj[r] = (bi == 0x7fffffff) ? 0 : bi;
#pragma unroll
        for (int k = 0; k < 4; ++k)
            if (ii[k] == bi) { vv[k] = CUDART_INF_F; ii[k] = 0x7fffffff; }
    }

    float4* zr = reinterpret_cast<float4*>(out + (size_t)row * D);
    float4 z0 = zr[lane], z1 = zr[lane + 32];
    float s4[4];
#pragma unroll
    for (int j = 0; j < 4; ++j) {
        const float4* ej = reinterpret_cast<const float4*>(cb + (size_t)jj[j] * D);
        float4 a = ej[lane];
        float4 c = ej[lane + 32];
        float s = 0.f;
        s = fmaf(z0.x, a.x, s); s = fmaf(z0.y, a.y, s);
        s = fmaf(z0.z, a.z, s); s = fmaf(z0.w, a.w, s);
        s = fmaf(z1.x, c.x, s); s = fmaf(z1.y, c.y, s);
        s = fmaf(z1.z, c.z, s); s = fmaf(z1.w, c.w, s);
        s4[j] = s;
    }
#pragma unroll
    for (int off = 16; off > 0; off >>= 1) {
#pragma unroll
        for (int j = 0; j < 4; ++j)
            s4[j] += __shfl_xor_sync(0xffffffffu, s4[j], off);
    }
    float best = CUDART_INF_F; int bi = 0x7fffffff;
#pragma unroll
    for (int j = 0; j < 4; ++j) {
        float dj = g_cn[jj[j]] - 2.f * s4[j];
        if (dj < best || (dj == best && jj[j] < bi)) { best = dj; bi = jj[j]; }
    }

    const float4* ew = reinterpret_cast<const float4*>(cb + (size_t)bi * D);
    float ls = 0.f;
    {
        float4 qv = ew[lane];
        zr[lane] = qv;
        float dx = z0.x - qv.x, dy = z0.y - qv.y;
        float dz = z0.z - qv.z, dw = z0.w - qv.w;
        ls += dx * dx + dy * dy + dz * dz + dw * dw;
        qv = ew[lane + 32];
        zr[lane + 32] = qv;
        dx = z1.x - qv.x; dy = z1.y - qv.y;
        dz = z1.z - qv.z; dw = z1.w - qv.w;
        ls += dx * dx + dy * dy + dz * dz + dw * dw;
    }
#pragma unroll
    for (int off = 16; off > 0; off >>= 1)
        ls += __shfl_xor_sync(0xffffffffu, ls, off);
    if (lane == 0) wloss[warp] = ls;
    __syncthreads();
    if (threadIdx.x == 0) {
        float t = 0.f;
#pragma unroll
        for (int w = 0; w < 8; ++w) t += wloss[w];
        g_part[blockIdx.x] = t;
    }
}

// ============================================================================
// Kernel 4: finalize losses (4096 partials, deterministic tree)
// ============================================================================
__global__ __launch_bounds__(1024)
void finalize_kernel(float* __restrict__ out, int out_size, float inv_count) {
    __shared__ float sr[1024];
    int t = threadIdx.x;
    float s = 0.f;
#pragma unroll
    for (int p = 0; p < 4; ++p) s += g_part[t + p * 1024];
    sr[t] = s;
    __syncthreads();
    for (int st = 512; st > 0; st >>= 1) {
        if (t < st) sr[t] += sr[t + st];
        __syncthreads();
    }
    if (t == 0) {
        float m = sr[0] * inv_count;
        out[out_size - 2] = m;
        out[out_size - 1] = m;
    }
}

// ============================================================================
extern "C" void kernel_launch(void* const* d_in, const int* in_sizes, int n_in,
                              void* d_out, int out_size) {
    const float* x  = (const float*)d_in[0];
    const float* W  = (const float*)d_in[1];
    const float* b  = (const float*)d_in[2];
    const float* cb = (const float*)d_in[3];

    int M      = in_sizes[0] / D;   // 32768
    int Kcodes = in_sizes[3] / D;   // 8192
    int NT     = Kcodes / 128;      // 64
    float* out = (float*)d_out;

    cudaFuncSetAttribute(dist_mma_kernel,
                         cudaFuncAttributeMaxDynamicSharedMemorySize, DIST_SMEM);
    cudaFuncSetAttribute(proj_cnsplit_kernel,
                         cudaFuncAttributeMaxDynamicSharedMemorySize, PROJ_SMEM);

    // 1. fused projection + codebook norms/split (overlapped in one launch)
    dim3 pg(M / BM, 3);
    proj_cnsplit_kernel<<<pg, NTHREADS, PROJ_SMEM>>>(x, W, b, cb, out);

    // 2. HMMA distance GEMM (1-term, CTA 64x128, 4 CTAs/SM, frag pipelined)
    dist_mma_kernel<<<dim3(M / 64, NT), 128, DIST_SMEM>>>(Kcodes);

    // 3. fused top-4 select + exact rescore + gather + loss partials
    rescore_gather_kernel<<<M / 8, 256>>>(out, cb, NT);

    // 4. finalize
    finalize_kernel<<<1, 1024>>>(out, out_size, 1.0f / (float)(M * D));
}